// round 5
// baseline (speedup 1.0000x reference)
#include <cuda_runtime.h>
#include <cuda_bf16.h>

// out[row,m] = ( fp32FWHT_m( sum_d fma-chain x[row,d]*W[m,d] ) * (1/sqrt(128)) > 0 ) ? 1 : 0
//
// Bit-exact vs reference (rel_err == 0.0 verified R2-R4): one fp32 accumulator
// per output element, strictly sequential fma.rn over d=0..1023 (k-tiles
// ascending, k ascending within tile), fp32 FWHT in reference butterfly order,
// fp32 scale, then >0.
//
// R5: occupancy push. BM=64, 4x8 microtile (32 acc regs), launch_bounds(256,3)
// -> 24 warps/SM (was 16). Double-buffered smem tiles, ONE barrier per k-tile.
// Warp mapping makes B-reads broadcast (1 wavefront) and A-reads 2 wavefronts.
//
// x [32768,1024] fp32, W [128,1024] fp32, out [32768,128] fp32.

#define MOUT 128
#define BM   64
#define BK   16

__global__ void __launch_bounds__(256, 3)
gemm_fwht_sign_kernel(const float* __restrict__ x, const float* __restrict__ W,
                      float* __restrict__ out, int K) {
    // smem: two GEMM tile buffers (12KB each) overlaid with FWHT buffer (33792B)
    __shared__ __align__(16) char smbuf[BM * (MOUT + 4) * 4];   // 33792 B
    // buffer p: As_p = smbuf + p*12288  [BK][BM], Bs_p = +4096 [BK][MOUT]
    float (*hb)[MOUT + 4] = reinterpret_cast<float(*)[MOUT + 4]>(smbuf);

    const int tid = threadIdx.x;      // 0..255
    const int tr  = tid & 15;         // rows tr*4 .. tr*4+3   (A: 2 wf/warp)
    const int tc  = tid >> 4;         // cols tc*8 .. tc*8+7   (B: broadcast)
    const int block_row = blockIdx.x * BM;

    const int r0 = tid >> 2;          // 0..63
    const int q0 = tid & 3;

    const float4* xA  = (const float4*)(x + (size_t)(block_row + r0) * K) + q0;
    const float4* wB0 = (const float4*)(W + (size_t)r0 * K) + q0;
    const float4* wB1 = (const float4*)(W + (size_t)(r0 + 64) * K) + q0;

    float acc[4][8];
#pragma unroll
    for (int i = 0; i < 4; ++i)
#pragma unroll
        for (int j = 0; j < 8; ++j) acc[i][j] = 0.0f;

    const int nkt = K / BK;           // 64
    const int kc  = q0 * 4;

    // prologue: stage tile 0 into buffer 0
    {
        float (*As)[BM]   = reinterpret_cast<float(*)[BM]>(smbuf);
        float (*Bs)[MOUT] = reinterpret_cast<float(*)[MOUT]>(smbuf + 4096);
        float4 pa = xA[0], pb0 = wB0[0], pb1 = wB1[0];
        As[kc + 0][r0] = pa.x;  As[kc + 1][r0] = pa.y;
        As[kc + 2][r0] = pa.z;  As[kc + 3][r0] = pa.w;
        Bs[kc + 0][r0] = pb0.x; Bs[kc + 1][r0] = pb0.y;
        Bs[kc + 2][r0] = pb0.z; Bs[kc + 3][r0] = pb0.w;
        Bs[kc + 0][r0 + 64] = pb1.x; Bs[kc + 1][r0 + 64] = pb1.y;
        Bs[kc + 2][r0 + 64] = pb1.z; Bs[kc + 3][r0 + 64] = pb1.w;
    }
    __syncthreads();

    for (int kt = 0; kt < nkt; ++kt) {
        const int cur = kt & 1;
        float (*As)[BM]   = reinterpret_cast<float(*)[BM]>(smbuf + cur * 12288);
        float (*Bs)[MOUT] = reinterpret_cast<float(*)[MOUT]>(smbuf + cur * 12288 + 4096);

        // prefetch next tile into registers (LDG overlaps compute below)
        float4 pa, pb0, pb1;
        const bool more = (kt + 1 < nkt);
        if (more) {
            const int off = (kt + 1) * (BK / 4);
            pa = xA[off]; pb0 = wB0[off]; pb1 = wB1[off];
        }

        // sequential k accumulation; one fp32 fma chain per output element
#pragma unroll
        for (int k = 0; k < BK; ++k) {
            const float4 a  = *(const float4*)&As[k][tr * 4];
            const float4 b0 = *(const float4*)&Bs[k][tc * 8];
            const float4 b1 = *(const float4*)&Bs[k][tc * 8 + 4];
            const float av[4] = {a.x, a.y, a.z, a.w};
            const float bv[8] = {b0.x, b0.y, b0.z, b0.w, b1.x, b1.y, b1.z, b1.w};
#pragma unroll
            for (int i = 0; i < 4; ++i)
#pragma unroll
                for (int j = 0; j < 8; ++j)
                    acc[i][j] = fmaf(av[i], bv[j], acc[i][j]);
        }

        // stage next tile into the other buffer, then single barrier
        if (more) {
            float (*An)[BM]   = reinterpret_cast<float(*)[BM]>(smbuf + (cur ^ 1) * 12288);
            float (*Bn)[MOUT] = reinterpret_cast<float(*)[MOUT]>(smbuf + (cur ^ 1) * 12288 + 4096);
            An[kc + 0][r0] = pa.x;  An[kc + 1][r0] = pa.y;
            An[kc + 2][r0] = pa.z;  An[kc + 3][r0] = pa.w;
            Bn[kc + 0][r0] = pb0.x; Bn[kc + 1][r0] = pb0.y;
            Bn[kc + 2][r0] = pb0.z; Bn[kc + 3][r0] = pb0.w;
            Bn[kc + 0][r0 + 64] = pb1.x; Bn[kc + 1][r0 + 64] = pb1.y;
            Bn[kc + 2][r0 + 64] = pb1.z; Bn[kc + 3][r0 + 64] = pb1.w;
        }
        __syncthreads();
    }

    // ---- epilogue: fp32 FWHT along m (reference butterfly order) + sign ----
    const float scale = 0.08838834764831844f;   // fp32( 1/sqrt(128) )

    // dump accumulators to the row buffer (overlays GEMM tiles; barrier above
    // guarantees all tile reads are done)
#pragma unroll
    for (int i = 0; i < 4; ++i)
#pragma unroll
        for (int j = 0; j < 8; ++j)
            hb[tr * 4 + i][tc * 8 + j] = acc[i][j];
    __syncthreads();

    for (int half = 1; half < MOUT; half <<= 1) {
#pragma unroll
        for (int p = 0; p < 16; ++p) {          // 64 rows * 64 pairs = 4096 / 256
            const int pidx = tid + p * 256;
            const int row = pidx >> 6;
            const int t   = pidx & 63;
            const int j   = ((t & ~(half - 1)) << 1) | (t & (half - 1));
            const float a = hb[row][j];
            const float b = hb[row][j + half];
            hb[row][j]        = a + b;
            hb[row][j + half] = a - b;
        }
        __syncthreads();
    }

#pragma unroll
    for (int p = 0; p < 8; ++p) {               // 64*128 floats = 2048 float4
        const int f4  = tid + p * 256;
        const int row = f4 >> 5;
        const int c   = (f4 & 31) * 4;
        float4 v = *(const float4*)&hb[row][c];
        float4 o;
        o.x = (v.x * scale > 0.0f) ? 1.0f : 0.0f;
        o.y = (v.y * scale > 0.0f) ? 1.0f : 0.0f;
        o.z = (v.z * scale > 0.0f) ? 1.0f : 0.0f;
        o.w = (v.w * scale > 0.0f) ? 1.0f : 0.0f;
        *(float4*)(out + (size_t)(block_row + row) * MOUT + c) = o;
    }
}

extern "C" void kernel_launch(void* const* d_in, const int* in_sizes, int n_in,
                              void* d_out, int out_size) {
    const float* x = (const float*)d_in[0];   // [rows, K]
    const float* W = (const float*)d_in[1];   // [128, K]
    float* out = (float*)d_out;               // [rows, 128]

    const int K = in_sizes[1] / MOUT;         // 1024
    const int rows = in_sizes[0] / K;         // 32768

    gemm_fwht_sign_kernel<<<rows / BM, 256>>>(x, W, out, K);
}